// round 2
// baseline (speedup 1.0000x reference)
#include <cuda_runtime.h>
#include <cuda_bf16.h>

#define N_NODES 100000
#define E_EDGES 1250000
#define DIM     64
#define NL      3

// ---- scratch (no allocations allowed) ----
__device__ float g_w[NL + 1];                 // softmax(alpha)
__device__ float g_deg[N_NODES];
__device__ float g_dis[N_NODES];
__device__ float g_ew[E_EDGES];
__device__ float g_x1[N_NODES * DIM];
__device__ float g_x2[N_NODES * DIM];
__device__ float g_out[N_NODES * DIM];

// softmax over 4 alphas, single thread
__global__ void k_softmax(const float* __restrict__ alpha) {
    if (threadIdx.x == 0) {
        float m = alpha[0];
        for (int i = 1; i <= NL; i++) m = fmaxf(m, alpha[i]);
        float s = 0.f;
        float e[NL + 1];
        for (int i = 0; i <= NL; i++) { e[i] = __expf(alpha[i] - m); s += e[i]; }
        for (int i = 0; i <= NL; i++) g_w[i] = e[i] / s;
    }
}

__global__ void k_zero(float* __restrict__ p, int n) {
    int i = blockIdx.x * blockDim.x + threadIdx.x;
    int stride = gridDim.x * blockDim.x;
    for (; i < n; i += stride) p[i] = 0.f;
}

__global__ void k_deg(const int* __restrict__ edge_index) {
    int e = blockIdx.x * blockDim.x + threadIdx.x;
    if (e < E_EDGES) {
        int t = edge_index[E_EDGES + e];   // dst row
        atomicAdd(&g_deg[t], 1.0f);
    }
}

__global__ void k_dis() {
    int i = blockIdx.x * blockDim.x + threadIdx.x;
    if (i < N_NODES) {
        float d = g_deg[i];
        g_dis[i] = (d > 0.f) ? rsqrtf(d) : 0.f;
    }
}

__global__ void k_edgeweight(const int* __restrict__ edge_index) {
    int e = blockIdx.x * blockDim.x + threadIdx.x;
    if (e < E_EDGES) {
        int s = edge_index[e];
        int t = edge_index[E_EDGES + e];
        g_ew[e] = g_dis[s] * g_dis[t];
    }
}

__global__ void k_init_out(const float* __restrict__ emb) {
    int i = blockIdx.x * blockDim.x + threadIdx.x;
    if (i < N_NODES * DIM) g_out[i] = g_w[0] * emb[i];
}

// scatter: xout[dst,:] += ew[e] * xin[src,:]. One thread per (edge, dim).
__global__ void k_scatter(const int* __restrict__ edge_index,
                          const float* __restrict__ xin,
                          float* __restrict__ xout) {
    long long tid = (long long)blockIdx.x * blockDim.x + threadIdx.x;
    if (tid < (long long)E_EDGES * DIM) {
        int e = (int)(tid >> 6);
        int d = (int)(tid & 63);
        int s = __ldg(&edge_index[e]);
        int t = __ldg(&edge_index[E_EDGES + e]);
        float v = g_ew[e] * xin[(long long)s * DIM + d];
        atomicAdd(&xout[(long long)t * DIM + d], v);
    }
}

__global__ void k_accum(const float* __restrict__ x, int widx) {
    int i = blockIdx.x * blockDim.x + threadIdx.x;
    if (i < N_NODES * DIM) g_out[i] += g_w[widx] * x[i];
}

// one warp per labeled edge: dot(out[a], out[b]) over D=64
__global__ void k_dot(const int* __restrict__ eli, float* __restrict__ res) {
    int gtid = blockIdx.x * blockDim.x + threadIdx.x;
    int e = gtid >> 5;
    int lane = gtid & 31;
    if (e < E_EDGES) {
        int a = __ldg(&eli[e]);
        int b = __ldg(&eli[E_EDGES + e]);
        const float* pa = g_out + (long long)a * DIM;
        const float* pb = g_out + (long long)b * DIM;
        float sum = pa[lane] * pb[lane] + pa[lane + 32] * pb[lane + 32];
        #pragma unroll
        for (int off = 16; off > 0; off >>= 1)
            sum += __shfl_xor_sync(0xffffffffu, sum, off);
        if (lane == 0) res[e] = sum;
    }
}

extern "C" void kernel_launch(void* const* d_in, const int* in_sizes, int n_in,
                              void* d_out, int out_size) {
    const int*   edge_index = (const int*)d_in[0];
    const int*   edge_label = (const int*)d_in[1];
    const float* emb        = (const float*)d_in[2];
    const float* alpha      = (const float*)d_in[3];
    float*       res        = (float*)d_out;

    float *x1, *x2, *degp;
    cudaGetSymbolAddress((void**)&x1,   g_x1);
    cudaGetSymbolAddress((void**)&x2,   g_x2);
    cudaGetSymbolAddress((void**)&degp, g_deg);

    const int TB = 256;
    const int ND = N_NODES * DIM;
    const long long ED = (long long)E_EDGES * DIM;

    k_softmax<<<1, 32>>>(alpha);

    // degree + normalization weights
    k_zero<<<(N_NODES + TB - 1) / TB, TB>>>(degp, N_NODES);
    k_deg<<<(E_EDGES + TB - 1) / TB, TB>>>(edge_index);
    k_dis<<<(N_NODES + TB - 1) / TB, TB>>>();
    k_edgeweight<<<(E_EDGES + TB - 1) / TB, TB>>>(edge_index);

    // out = w0 * emb
    k_init_out<<<(ND + TB - 1) / TB, TB>>>(emb);

    int scatter_blocks = (int)((ED + TB - 1) / TB);
    int nd_blocks = (ND + TB - 1) / TB;

    // layer 1: emb -> x1
    k_zero<<<nd_blocks, TB>>>(x1, ND);
    k_scatter<<<scatter_blocks, TB>>>(edge_index, emb, x1);
    k_accum<<<nd_blocks, TB>>>(x1, 1);

    // layer 2: x1 -> x2
    k_zero<<<nd_blocks, TB>>>(x2, ND);
    k_scatter<<<scatter_blocks, TB>>>(edge_index, x1, x2);
    k_accum<<<nd_blocks, TB>>>(x2, 2);

    // layer 3: x2 -> x1
    k_zero<<<nd_blocks, TB>>>(x1, ND);
    k_scatter<<<scatter_blocks, TB>>>(edge_index, x2, x1);
    k_accum<<<nd_blocks, TB>>>(x1, 3);

    // per-edge dot over edge_label_index
    long long dot_threads = (long long)E_EDGES * 32;
    k_dot<<<(int)((dot_threads + TB - 1) / TB), TB>>>(edge_label, res);
}

// round 3
// speedup vs baseline: 3.9395x; 3.9395x over previous
#include <cuda_runtime.h>
#include <cuda_bf16.h>

#define N_NODES 100000
#define E_EDGES 1250000
#define DIM     64
#define NL      3
#define SCAN_B  256
#define SCAN_NBLK ((N_NODES + SCAN_B - 1) / SCAN_B)   // 391

// ---- scratch (no allocations allowed) ----
__device__ float g_w[NL + 1];
__device__ int   g_cnt[N_NODES];
__device__ int   g_cur[N_NODES];
__device__ int   g_excl[N_NODES];
__device__ int   g_bsum[512];
__device__ int   g_boff[512];
__device__ int   g_rowptr[N_NODES + 1];
__device__ int   g_csrc[E_EDGES];
__device__ float g_cw[E_EDGES];
__device__ float g_dis[N_NODES];
__device__ float g_x1[N_NODES * DIM];
__device__ float g_x2[N_NODES * DIM];
__device__ float g_out[N_NODES * DIM];

__global__ void k_softmax(const float* __restrict__ alpha) {
    if (threadIdx.x == 0) {
        float m = alpha[0];
        for (int i = 1; i <= NL; i++) m = fmaxf(m, alpha[i]);
        float s = 0.f, e[NL + 1];
        for (int i = 0; i <= NL; i++) { e[i] = __expf(alpha[i] - m); s += e[i]; }
        for (int i = 0; i <= NL; i++) g_w[i] = e[i] / s;
    }
}

__global__ void k_zero_counts() {
    int i = blockIdx.x * blockDim.x + threadIdx.x;
    if (i < N_NODES) { g_cnt[i] = 0; g_cur[i] = 0; }
}

__global__ void k_count(const int* __restrict__ edge_index) {
    int e = blockIdx.x * blockDim.x + threadIdx.x;
    if (e < E_EDGES) atomicAdd(&g_cnt[edge_index[E_EDGES + e]], 1);
}

__global__ void k_dis() {
    int i = blockIdx.x * blockDim.x + threadIdx.x;
    if (i < N_NODES) {
        int d = g_cnt[i];
        g_dis[i] = (d > 0) ? rsqrtf((float)d) : 0.f;
    }
}

// exclusive scan stage 1: per-block scan + block sums
__global__ void k_scan1() {
    __shared__ int sh[SCAN_B];
    int t = threadIdx.x, b = blockIdx.x, i = b * SCAN_B + t;
    int v = (i < N_NODES) ? g_cnt[i] : 0;
    sh[t] = v; __syncthreads();
    #pragma unroll
    for (int off = 1; off < SCAN_B; off <<= 1) {
        int u = (t >= off) ? sh[t - off] : 0;
        __syncthreads();
        sh[t] += u;
        __syncthreads();
    }
    if (i < N_NODES) g_excl[i] = sh[t] - v;
    if (t == SCAN_B - 1) g_bsum[b] = sh[t];
}

// stage 2: scan the 391 block sums in a single 512-thread block
__global__ void k_scan2() {
    __shared__ int sh[512];
    int t = threadIdx.x;
    int v = (t < SCAN_NBLK) ? g_bsum[t] : 0;
    sh[t] = v; __syncthreads();
    #pragma unroll
    for (int off = 1; off < 512; off <<= 1) {
        int u = (t >= off) ? sh[t - off] : 0;
        __syncthreads();
        sh[t] += u;
        __syncthreads();
    }
    if (t < SCAN_NBLK) g_boff[t] = sh[t] - v;
}

// stage 3: combine
__global__ void k_scan3() {
    int i = blockIdx.x * blockDim.x + threadIdx.x;
    if (i < N_NODES) g_rowptr[i] = g_excl[i] + g_boff[i / SCAN_B];
    if (i == 0) g_rowptr[N_NODES] = E_EDGES;
}

// fill CSR: edge e -> slot in dst's range; weight = dis[src]*dis[dst]
__global__ void k_fill(const int* __restrict__ edge_index) {
    int e = blockIdx.x * blockDim.x + threadIdx.x;
    if (e < E_EDGES) {
        int s = edge_index[e];
        int t = edge_index[E_EDGES + e];
        int pos = g_rowptr[t] + atomicAdd(&g_cur[t], 1);
        g_csrc[pos] = s;
        g_cw[pos]   = g_dis[s] * g_dis[t];
    }
}

// Gather propagation: one warp per dst node, float2 per lane (256B row).
// Fused epilogue: xout = acc; out (+)= w[widx]*acc [+ w0*emb on first layer].
template<bool FIRST>
__global__ void k_gather(const float* __restrict__ xin,
                         float* __restrict__ xout,
                         const float* __restrict__ emb,
                         int widx) {
    int t = threadIdx.x;
    int node = blockIdx.x * 8 + (t >> 5);
    int lane = t & 31;
    if (node >= N_NODES) return;
    int i0 = g_rowptr[node], i1 = g_rowptr[node + 1];
    float ax = 0.f, ay = 0.f;
    for (int i = i0; i < i1; i++) {
        int   s = __ldg(&g_csrc[i]);
        float w = __ldg(&g_cw[i]);
        float2 v = *reinterpret_cast<const float2*>(xin + (size_t)s * DIM + lane * 2);
        ax = fmaf(w, v.x, ax);
        ay = fmaf(w, v.y, ay);
    }
    size_t o = (size_t)node * DIM + lane * 2;
    *reinterpret_cast<float2*>(xout + o) = make_float2(ax, ay);
    float wl = g_w[widx];
    float2* po = reinterpret_cast<float2*>(g_out + o);
    if (FIRST) {
        float2 e2 = *reinterpret_cast<const float2*>(emb + o);
        float w0 = g_w[0];
        *po = make_float2(fmaf(w0, e2.x, wl * ax), fmaf(w0, e2.y, wl * ay));
    } else {
        float2 c = *po;
        *po = make_float2(fmaf(wl, ax, c.x), fmaf(wl, ay, c.y));
    }
}

// dot: 16 lanes per edge, float4 per lane (256B coalesced row reads)
__global__ void k_dot(const int* __restrict__ eli, float* __restrict__ res) {
    int gt = blockIdx.x * blockDim.x + threadIdx.x;
    int e = gt >> 4, l = gt & 15;
    if (e >= E_EDGES) return;
    int a = __ldg(&eli[e]);
    int b = __ldg(&eli[E_EDGES + e]);
    float4 va = *reinterpret_cast<const float4*>(g_out + (size_t)a * DIM + l * 4);
    float4 vb = *reinterpret_cast<const float4*>(g_out + (size_t)b * DIM + l * 4);
    float s = va.x * vb.x + va.y * vb.y + va.z * vb.z + va.w * vb.w;
    #pragma unroll
    for (int off = 8; off > 0; off >>= 1)
        s += __shfl_xor_sync(0xffffffffu, s, off);
    if (l == 0) res[e] = s;
}

extern "C" void kernel_launch(void* const* d_in, const int* in_sizes, int n_in,
                              void* d_out, int out_size) {
    const int*   edge_index = (const int*)d_in[0];
    const int*   edge_label = (const int*)d_in[1];
    const float* emb        = (const float*)d_in[2];
    const float* alpha      = (const float*)d_in[3];
    float*       res        = (float*)d_out;

    float *x1, *x2;
    cudaGetSymbolAddress((void**)&x1, g_x1);
    cudaGetSymbolAddress((void**)&x2, g_x2);

    const int TB = 256;
    const int nblkN = (N_NODES + TB - 1) / TB;
    const int nblkE = (E_EDGES + TB - 1) / TB;
    const int nblkG = (N_NODES + 7) / 8;          // 8 nodes per 256-thread block

    k_softmax<<<1, 32>>>(alpha);

    // CSR build
    k_zero_counts<<<nblkN, TB>>>();
    k_count<<<nblkE, TB>>>(edge_index);
    k_dis<<<nblkN, TB>>>();
    k_scan1<<<SCAN_NBLK, SCAN_B>>>();
    k_scan2<<<1, 512>>>();
    k_scan3<<<nblkN, TB>>>();
    k_fill<<<nblkE, TB>>>(edge_index);

    // propagation (gather, no fp atomics), out-accum fused
    k_gather<true ><<<nblkG, TB>>>(emb, x1, emb, 1);
    k_gather<false><<<nblkG, TB>>>(x1, x2, nullptr, 2);
    k_gather<false><<<nblkG, TB>>>(x2, x1, nullptr, 3);

    // per-edge dot over edge_label_index
    long long dot_threads = (long long)E_EDGES * 16;
    k_dot<<<(int)((dot_threads + TB - 1) / TB), TB>>>(edge_label, res);
}

// round 4
// speedup vs baseline: 4.0070x; 1.0171x over previous
#include <cuda_runtime.h>
#include <cuda_bf16.h>

#define N_NODES 100000
#define E_EDGES 1250000
#define DIM     64
#define NL      3
#define SCAN_B  256
#define SCAN_NBLK ((N_NODES + SCAN_B - 1) / SCAN_B)   // 391

// ---- scratch (no allocations allowed) ----
__device__ float g_w[NL + 1];
__device__ int   g_cnt[N_NODES];
__device__ int   g_cur[N_NODES];
__device__ int   g_excl[N_NODES];
__device__ int   g_bsum[512];
__device__ int   g_boff[512];
__device__ int   g_rowptr[N_NODES + 1];
__device__ int   g_csrc[E_EDGES];
__device__ float g_cw[E_EDGES];
__device__ float g_dis[N_NODES];
__device__ float g_x1[N_NODES * DIM];
__device__ float g_x2[N_NODES * DIM];
__device__ float g_out[N_NODES * DIM];

// zero counters; block 0 thread 0 also does the 4-way softmax
__global__ void k_prep(const float* __restrict__ alpha) {
    int i = blockIdx.x * blockDim.x + threadIdx.x;
    if (i < N_NODES) { g_cnt[i] = 0; g_cur[i] = 0; }
    if (i == 0) {
        float m = alpha[0];
        for (int j = 1; j <= NL; j++) m = fmaxf(m, alpha[j]);
        float s = 0.f, e[NL + 1];
        for (int j = 0; j <= NL; j++) { e[j] = __expf(alpha[j] - m); s += e[j]; }
        for (int j = 0; j <= NL; j++) g_w[j] = e[j] / s;
    }
}

__global__ void k_count(const int* __restrict__ edge_index) {
    int e = blockIdx.x * blockDim.x + threadIdx.x;
    if (e < E_EDGES) atomicAdd(&g_cnt[edge_index[E_EDGES + e]], 1);
}

// per-block scan + block sums; also computes dis = rsqrt(deg) (fused)
__global__ void k_scan1() {
    __shared__ int sh[SCAN_B];
    int t = threadIdx.x, b = blockIdx.x, i = b * SCAN_B + t;
    int v = (i < N_NODES) ? g_cnt[i] : 0;
    if (i < N_NODES) g_dis[i] = (v > 0) ? rsqrtf((float)v) : 0.f;
    sh[t] = v; __syncthreads();
    #pragma unroll
    for (int off = 1; off < SCAN_B; off <<= 1) {
        int u = (t >= off) ? sh[t - off] : 0;
        __syncthreads();
        sh[t] += u;
        __syncthreads();
    }
    if (i < N_NODES) g_excl[i] = sh[t] - v;
    if (t == SCAN_B - 1) g_bsum[b] = sh[t];
}

// scan the 391 block sums in a single 512-thread block
__global__ void k_scan2() {
    __shared__ int sh[512];
    int t = threadIdx.x;
    int v = (t < SCAN_NBLK) ? g_bsum[t] : 0;
    sh[t] = v; __syncthreads();
    #pragma unroll
    for (int off = 1; off < 512; off <<= 1) {
        int u = (t >= off) ? sh[t - off] : 0;
        __syncthreads();
        sh[t] += u;
        __syncthreads();
    }
    if (t < SCAN_NBLK) g_boff[t] = sh[t] - v;
}

__global__ void k_scan3() {
    int i = blockIdx.x * blockDim.x + threadIdx.x;
    if (i < N_NODES) g_rowptr[i] = g_excl[i] + g_boff[i / SCAN_B];
    if (i == 0) g_rowptr[N_NODES] = E_EDGES;
}

// fill CSR: edge e -> slot in dst's range; weight = dis[src]*dis[dst]
__global__ void k_fill(const int* __restrict__ edge_index) {
    int e = blockIdx.x * blockDim.x + threadIdx.x;
    if (e < E_EDGES) {
        int s = edge_index[e];
        int t = edge_index[E_EDGES + e];
        int pos = g_rowptr[t] + atomicAdd(&g_cur[t], 1);
        g_csrc[pos] = s;
        g_cw[pos]   = g_dis[s] * g_dis[t];
    }
}

// Gather propagation: one warp per dst node, float2 per lane (256B row).
// 4-way unroll -> 4 independent row gathers in flight per warp.
// Fused epilogue: xout = acc (unless LAST); out (+)= w[widx]*acc [+ w0*emb if FIRST].
template<bool FIRST, bool LAST>
__global__ void k_gather(const float* __restrict__ xin,
                         float* __restrict__ xout,
                         const float* __restrict__ emb,
                         int widx) {
    int t = threadIdx.x;
    int node = blockIdx.x * 8 + (t >> 5);
    int lane = t & 31;
    if (node >= N_NODES) return;
    int i0 = g_rowptr[node], i1 = g_rowptr[node + 1];
    float ax = 0.f, ay = 0.f;
    int i = i0;
    int lim = i1 - 3;
    for (; i < lim; i += 4) {
        int   s0 = __ldg(&g_csrc[i]);
        int   s1 = __ldg(&g_csrc[i + 1]);
        int   s2 = __ldg(&g_csrc[i + 2]);
        int   s3 = __ldg(&g_csrc[i + 3]);
        float w0 = __ldg(&g_cw[i]);
        float w1 = __ldg(&g_cw[i + 1]);
        float w2 = __ldg(&g_cw[i + 2]);
        float w3 = __ldg(&g_cw[i + 3]);
        float2 v0 = *reinterpret_cast<const float2*>(xin + (size_t)s0 * DIM + lane * 2);
        float2 v1 = *reinterpret_cast<const float2*>(xin + (size_t)s1 * DIM + lane * 2);
        float2 v2 = *reinterpret_cast<const float2*>(xin + (size_t)s2 * DIM + lane * 2);
        float2 v3 = *reinterpret_cast<const float2*>(xin + (size_t)s3 * DIM + lane * 2);
        ax = fmaf(w0, v0.x, ax); ay = fmaf(w0, v0.y, ay);
        ax = fmaf(w1, v1.x, ax); ay = fmaf(w1, v1.y, ay);
        ax = fmaf(w2, v2.x, ax); ay = fmaf(w2, v2.y, ay);
        ax = fmaf(w3, v3.x, ax); ay = fmaf(w3, v3.y, ay);
    }
    for (; i < i1; i++) {
        int   s = __ldg(&g_csrc[i]);
        float w = __ldg(&g_cw[i]);
        float2 v = *reinterpret_cast<const float2*>(xin + (size_t)s * DIM + lane * 2);
        ax = fmaf(w, v.x, ax);
        ay = fmaf(w, v.y, ay);
    }
    size_t o = (size_t)node * DIM + lane * 2;
    if (!LAST)
        *reinterpret_cast<float2*>(xout + o) = make_float2(ax, ay);
    float wl = g_w[widx];
    float2* po = reinterpret_cast<float2*>(g_out + o);
    if (FIRST) {
        float2 e2 = *reinterpret_cast<const float2*>(emb + o);
        float w0 = g_w[0];
        *po = make_float2(fmaf(w0, e2.x, wl * ax), fmaf(w0, e2.y, wl * ay));
    } else {
        float2 c = *po;
        *po = make_float2(fmaf(wl, ax, c.x), fmaf(wl, ay, c.y));
    }
}

// dot: 16 lanes per edge, float4 per lane (256B coalesced row reads)
__global__ void k_dot(const int* __restrict__ eli, float* __restrict__ res) {
    int gt = blockIdx.x * blockDim.x + threadIdx.x;
    int e = gt >> 4, l = gt & 15;
    if (e >= E_EDGES) return;
    int a = __ldg(&eli[e]);
    int b = __ldg(&eli[E_EDGES + e]);
    float4 va = *reinterpret_cast<const float4*>(g_out + (size_t)a * DIM + l * 4);
    float4 vb = *reinterpret_cast<const float4*>(g_out + (size_t)b * DIM + l * 4);
    float s = va.x * vb.x + va.y * vb.y + va.z * vb.z + va.w * vb.w;
    #pragma unroll
    for (int off = 8; off > 0; off >>= 1)
        s += __shfl_xor_sync(0xffffffffu, s, off);
    if (l == 0) res[e] = s;
}

extern "C" void kernel_launch(void* const* d_in, const int* in_sizes, int n_in,
                              void* d_out, int out_size) {
    const int*   edge_index = (const int*)d_in[0];
    const int*   edge_label = (const int*)d_in[1];
    const float* emb        = (const float*)d_in[2];
    const float* alpha      = (const float*)d_in[3];
    float*       res        = (float*)d_out;

    float *x1, *x2;
    cudaGetSymbolAddress((void**)&x1, g_x1);
    cudaGetSymbolAddress((void**)&x2, g_x2);

    const int TB = 256;
    const int nblkN = (N_NODES + TB - 1) / TB;
    const int nblkE = (E_EDGES + TB - 1) / TB;
    const int nblkG = (N_NODES + 7) / 8;          // 8 nodes per 256-thread block

    // CSR build
    k_prep<<<nblkN, TB>>>(alpha);
    k_count<<<nblkE, TB>>>(edge_index);
    k_scan1<<<SCAN_NBLK, SCAN_B>>>();
    k_scan2<<<1, 512>>>();
    k_scan3<<<nblkN, TB>>>();
    k_fill<<<nblkE, TB>>>(edge_index);

    // propagation (gather, no fp atomics), out-accum fused
    k_gather<true,  false><<<nblkG, TB>>>(emb, x1, emb, 1);
    k_gather<false, false><<<nblkG, TB>>>(x1, x2, nullptr, 2);
    k_gather<false, true ><<<nblkG, TB>>>(x2, x1, nullptr, 3);

    // per-edge dot over edge_label_index
    long long dot_threads = (long long)E_EDGES * 16;
    k_dot<<<(int)((dot_threads + TB - 1) / TB), TB>>>(edge_label, res);
}